// round 15
// baseline (speedup 1.0000x reference)
#include <cuda_runtime.h>
#include <math.h>

#define SEQ   4096
#define LW    24
#define EMBD  300
#define CHOUT 25
#define CHE   25
#define HIDN  512
#define INPD  325      // EMB + CH_OUT
#define EMBS  336      // padded K (21 * 16) for vectorized GEMM
#define NTAG  11
#define STARTT 9
#define STOPT  10
#define NEGV  -10000.0f
#define NGATE 2048     // 4*HIDN
#define SENT  0x7FC00ABCu   // NaN payload sentinel: h in (-1,1) can never be NaN

typedef unsigned long long u64;

// ---------------- static device scratch (no allocs allowed) ----------------
__device__ float g_emb[SEQ * EMBS];             // 5.5 MB  [t][k], cols >=325 zero
__device__ float g_W[2][NGATE * EMBS];          // 5.5 MB  padded Wih
__device__ float g_G[2][SEQ * NGATE];           // 64 MB   Wih@x + bih + bhh
__device__ float g_h[2][SEQ * HIDN];            // 16 MB   hidden states (L2-resident)
__device__ float g_feats[SEQ * 16];             // padded [t][tag]

// ---------------- helpers ----------------
__device__ __forceinline__ float4 ld_rlx4(const float4* p) {
    float4 v;
    asm volatile("ld.relaxed.gpu.global.v4.f32 {%0,%1,%2,%3}, [%4];"
                 : "=f"(v.x), "=f"(v.y), "=f"(v.z), "=f"(v.w) : "l"(p));
    return v;
}
__device__ __forceinline__ void st_rlx(float* p, float v) {
    asm volatile("st.relaxed.gpu.global.f32 [%0], %1;" :: "l"(p), "f"(v));
}
__device__ __forceinline__ u64 fma2(u64 a, u64 b, u64 c) {
    u64 d;
    asm("fma.rn.f32x2 %0, %1, %2, %3;" : "=l"(d) : "l"(a), "l"(b), "l"(c));
    return d;
}
__device__ __forceinline__ u64 add2(u64 a, u64 b) {
    u64 d;
    asm("add.rn.f32x2 %0, %1, %2;" : "=l"(d) : "l"(a), "l"(b));
    return d;
}
__device__ __forceinline__ void upk2(u64 v, float& lo, float& hi) {
    asm("mov.b64 {%0,%1}, %2;" : "=f"(lo), "=f"(hi) : "l"(v));
}
__device__ __forceinline__ u64 pk2(float lo, float hi) {
    u64 d;
    asm("mov.b64 %0, {%1,%2};" : "=l"(d) : "f"(lo), "f"(hi));
    return d;
}
__device__ __forceinline__ float sigf(float x) {
    return __fdividef(1.0f, 1.0f + __expf(-x));
}
__device__ __forceinline__ float tanh_fast(float x) {
    return __fdividef(2.0f, 1.0f + __expf(-2.0f * x)) - 1.0f;
}

// ---------------- poison hidden-state buffer (data-as-flag protocol) --------
// Launched AFTER the GEMM (R14 win): the 16MB sentinel image must be the
// freshest data in L2 when the LSTM's polls start.
__global__ void poison_kernel() {
    int i = blockIdx.x * blockDim.x + threadIdx.x;   // 1M float4 = 16 MB
    float s = __uint_as_float(SENT);
    ((float4*)&g_h[0][0])[i] = make_float4(s, s, s, s);
}

// ---------------- pad Wih into g_W (zero-filled K padding) ------------------
__global__ void padw_kernel(const float* __restrict__ Wf,
                            const float* __restrict__ Wb) {
    int i = blockIdx.x * blockDim.x + threadIdx.x;
    if (i >= NGATE * EMBS) return;
    int r = i / EMBS, k = i - r * EMBS;
    g_W[0][i] = (k < INPD) ? Wf[r * INPD + k] : 0.0f;
    g_W[1][i] = (k < INPD) ? Wb[r * INPD + k] : 0.0f;
}

// ---------------- char CNN + word-embedding gather --------------------------
__global__ void embed_kernel(const int* __restrict__ sentence,
                             const int* __restrict__ chars,
                             const float* __restrict__ word_emb,
                             const float* __restrict__ char_emb,
                             const float* __restrict__ conv_w,
                             const float* __restrict__ conv_b) {
    int s = blockIdx.x;
    int tid = threadIdx.x;
    __shared__ float ce[LW][CHE];
    __shared__ float co[CHOUT][26];
    __shared__ int   cidx[LW];

    if (tid < LW) cidx[tid] = chars[s * LW + tid];
    __syncthreads();
    for (int idx = tid; idx < LW * CHE; idx += blockDim.x) {
        int r = idx / CHE, e = idx % CHE;
        ce[r][e] = char_emb[cidx[r] * CHE + e];
    }
    __syncthreads();
    for (int idx = tid; idx < CHOUT * 26; idx += blockDim.x) {
        int o = idx / 26, p = idx % 26;
        float sum = 0.0f;
        #pragma unroll
        for (int kh = 0; kh < 3; kh++) {
            int r = p - 2 + kh;
            if (r >= 0 && r < LW) {
                const float* w = conv_w + (o * 3 + kh) * CHE;
                float ss = 0.0f;
                #pragma unroll
                for (int e = 0; e < CHE; e++) ss += ce[r][e] * w[e];
                sum += ss;
            }
        }
        co[o][p] = sum;
    }
    __syncthreads();
    if (tid < CHOUT) {
        float m = -3.4e38f;
        #pragma unroll
        for (int p = 0; p < 26; p++) m = fmaxf(m, co[tid][p]);
        g_emb[s * EMBS + EMBD + tid] = m + conv_b[tid];
    }
    if (tid < EMBS - INPD) g_emb[s * EMBS + INPD + tid] = 0.0f;  // zero K pad
    int wi = sentence[s];
    const float4* src = (const float4*)(word_emb + (size_t)wi * EMBD);
    float4* dst = (float4*)(g_emb + (size_t)s * EMBS);
    for (int i = tid; i < EMBD / 4; i += blockDim.x) dst[i] = src[i];
}

// ---------------- G = emb @ Wih^T + (bih + bhh) -----------------------------
// 128x128 tile, 256 threads, 8x8 microtile, packed f32x2 FMAs. (226us, kept.)
__global__ __launch_bounds__(256) void gemm_kernel(
    const float* __restrict__ bihf, const float* __restrict__ bhhf,
    const float* __restrict__ bihb, const float* __restrict__ bhhb) {
    int dir = blockIdx.z;
    const float* Wp = g_W[dir];
    const float* bih = dir ? bihb : bihf;
    const float* bhh = dir ? bhhb : bhhf;
    int bm = blockIdx.y * 128;
    int bn = blockIdx.x * 128;
    int tid = threadIdx.x;
    int tx = tid & 15, ty = tid >> 4;
    int lrow = tid >> 1, lk = (tid & 1) * 8;

    __shared__ __align__(16) float As[16][132];
    __shared__ __align__(16) float Bs[16][132];

    float bsum[8];
    #pragma unroll
    for (int j = 0; j < 4; j++) {
        int n0 = bn + tx * 4 + j, n1 = bn + 64 + tx * 4 + j;
        bsum[j] = bih[n0] + bhh[n0];
        bsum[4 + j] = bih[n1] + bhh[n1];
    }

    u64 acc[8][4] = {};

    for (int k0 = 0; k0 < EMBS; k0 += 16) {
        const float* ap = g_emb + (size_t)(bm + lrow) * EMBS + k0 + lk;
        const float* bp = Wp + (size_t)(bn + lrow) * EMBS + k0 + lk;
        float4 a0 = *(const float4*)ap;
        float4 a1 = *(const float4*)(ap + 4);
        float4 b0 = *(const float4*)bp;
        float4 b1 = *(const float4*)(bp + 4);
        __syncthreads();
        As[lk + 0][lrow] = a0.x; As[lk + 1][lrow] = a0.y;
        As[lk + 2][lrow] = a0.z; As[lk + 3][lrow] = a0.w;
        As[lk + 4][lrow] = a1.x; As[lk + 5][lrow] = a1.y;
        As[lk + 6][lrow] = a1.z; As[lk + 7][lrow] = a1.w;
        Bs[lk + 0][lrow] = b0.x; Bs[lk + 1][lrow] = b0.y;
        Bs[lk + 2][lrow] = b0.z; Bs[lk + 3][lrow] = b0.w;
        Bs[lk + 4][lrow] = b1.x; Bs[lk + 5][lrow] = b1.y;
        Bs[lk + 6][lrow] = b1.z; Bs[lk + 7][lrow] = b1.w;
        __syncthreads();
        #pragma unroll
        for (int kk = 0; kk < 16; kk++) {
            float4 af0 = *(const float4*)&As[kk][ty * 4];
            float4 af1 = *(const float4*)&As[kk][64 + ty * 4];
            float4 bf0 = *(const float4*)&Bs[kk][tx * 4];
            float4 bf1 = *(const float4*)&Bs[kk][64 + tx * 4];
            u64 bb0 = pk2(bf0.x, bf0.y), bb1 = pk2(bf0.z, bf0.w);
            u64 bb2 = pk2(bf1.x, bf1.y), bb3 = pk2(bf1.z, bf1.w);
            float aarr[8] = {af0.x, af0.y, af0.z, af0.w,
                             af1.x, af1.y, af1.z, af1.w};
            #pragma unroll
            for (int i = 0; i < 8; i++) {
                u64 aa = pk2(aarr[i], aarr[i]);
                acc[i][0] = fma2(aa, bb0, acc[i][0]);
                acc[i][1] = fma2(aa, bb1, acc[i][1]);
                acc[i][2] = fma2(aa, bb2, acc[i][2]);
                acc[i][3] = fma2(aa, bb3, acc[i][3]);
            }
        }
    }

    float* Gp = g_G[dir];
    #pragma unroll
    for (int i = 0; i < 8; i++) {
        int t = bm + ((i < 4) ? (ty * 4 + i) : (64 + ty * 4 + (i - 4)));
        float o[8];
        upk2(acc[i][0], o[0], o[1]); upk2(acc[i][1], o[2], o[3]);
        upk2(acc[i][2], o[4], o[5]); upk2(acc[i][3], o[6], o[7]);
        float4 v0 = make_float4(o[0] + bsum[0], o[1] + bsum[1],
                                o[2] + bsum[2], o[3] + bsum[3]);
        float4 v1 = make_float4(o[4] + bsum[4], o[5] + bsum[5],
                                o[6] + bsum[6], o[7] + bsum[7]);
        *(float4*)(Gp + (size_t)t * NGATE + bn + tx * 4) = v0;
        *(float4*)(Gp + (size_t)t * NGATE + bn + 64 + tx * 4) = v1;
    }
}

// ---------------- persistent BiLSTM recurrence -------------------------------
// Fan-in restructure: 64 blocks total (32/dir) x 512 threads. Block b owns
// 16 h outputs -> 64 gate rows. Per-THREAD work is byte-identical to the
// proven R8 structure (64 cols x 1 gate row, wgt[16], same poll loop, same
// 3-shfl reduce). Gates on tid<16; store = 16 contiguous lanes = one 64B
// wavefront (a full L2 line). Halves producer-store events per step (32 vs
// 64) -> smaller max-order-statistic and slower skew accumulation.
__global__ __launch_bounds__(512, 1) void lstm_kernel(
    const float* __restrict__ Whhf, const float* __restrict__ Whhb) {
    int dir = blockIdx.x >> 5;
    int b = blockIdx.x & 31;
    int tid = threadIdx.x;
    int lr = tid >> 3;     // local gate row 0..63
    int cg = tid & 7;      // column group (64 cols each)
    int gate = lr >> 4, jj = lr & 15;
    int grow = gate * HIDN + b * 16 + jj;
    const float* Whh = dir ? Whhb : Whhf;

    // 64 weights per thread in registers for the whole sequence
    ulonglong2 wgt[16];
    {
        const ulonglong2* wsrc = (const ulonglong2*)(Whh + (size_t)grow * HIDN + cg * 64);
        #pragma unroll
        for (int q = 0; q < 16; q++) wgt[q] = wsrc[q];
    }

    __shared__ float4 hs4[8 * 17];   // swizzled h_prev
    __shared__ float  gsum[64];

    const float* Gp = g_G[dir];
    float* hp = g_h[dir];
    float cstate = 0.0f;
    float gn0 = 0.f, gn1 = 0.f, gn2 = 0.f, gn3 = 0.f;

    // prefetch G for step 0 (streaming loads: do not pollute L2)
    if (tid < 16) {
        int t0 = dir ? (SEQ - 1) : 0;
        const float* gr = Gp + (size_t)t0 * NGATE + b * 16 + tid;
        gn0 = __ldcs(gr);        gn1 = __ldcs(gr + 512);
        gn2 = __ldcs(gr + 1024); gn3 = __ldcs(gr + 1536);
    }

    for (int s = 0; s < SEQ; s++) {
        int t = dir ? (SEQ - 1 - s) : s;
        float gi = gn0, gf = gn1, gg = gn2, go = gn3;
        if (tid < 16 && s + 1 < SEQ) {
            int tn = dir ? (t - 1) : (t + 1);
            const float* gr = Gp + (size_t)tn * NGATE + b * 16 + tid;
            gn0 = __ldcs(gr);        gn1 = __ldcs(gr + 512);
            gn2 = __ldcs(gr + 1024); gn3 = __ldcs(gr + 1536);
        }

        if (s > 0) {
            int pt = dir ? (t + 1) : (t - 1);
            if (tid < 128) {
                const float4* src = (const float4*)(hp + (size_t)pt * HIDN) + tid;
                float4 v;
                do {
                    v = ld_rlx4(src);
                } while (__float_as_uint(v.x) == SENT || __float_as_uint(v.y) == SENT ||
                         __float_as_uint(v.z) == SENT || __float_as_uint(v.w) == SENT);
                hs4[(tid >> 4) * 17 + (tid & 15)] = v;
            }
        } else {
            if (tid < 136) hs4[tid] = make_float4(0.f, 0.f, 0.f, 0.f);
        }
        __syncthreads();

        // partial dot: 64 columns per thread via packed f32x2 FMAs
        const ulonglong2* hrow = (const ulonglong2*)(hs4 + cg * 17);
        u64 a0 = 0ULL, a1 = 0ULL, a2 = 0ULL, a3 = 0ULL;
        #pragma unroll
        for (int q = 0; q < 16; q += 2) {
            ulonglong2 h0 = hrow[q];
            ulonglong2 h1 = hrow[q + 1];
            a0 = fma2(wgt[q].x, h0.x, a0);
            a1 = fma2(wgt[q].y, h0.y, a1);
            a2 = fma2(wgt[q + 1].x, h1.x, a2);
            a3 = fma2(wgt[q + 1].y, h1.y, a3);
        }
        float lo, hi;
        upk2(add2(add2(a0, a1), add2(a2, a3)), lo, hi);
        float acc = lo + hi;
        acc += __shfl_xor_sync(0xffffffffu, acc, 4);
        acc += __shfl_xor_sync(0xffffffffu, acc, 2);
        acc += __shfl_xor_sync(0xffffffffu, acc, 1);
        if (cg == 0) gsum[lr] = acc;
        __syncthreads();

        // gates: single warp, lanes 0..15 (independent MUFU chains overlap)
        if (tid < 16) {
            float vi = sigf(gi + gsum[tid]);
            float vf = sigf(gf + gsum[16 + tid]);
            float vg = tanh_fast(gg + gsum[32 + tid]);
            float vo = sigf(go + gsum[48 + tid]);
            cstate = vf * cstate + vi * vg;
            float h = vo * tanh_fast(cstate);
            // 16 lanes, contiguous 64B: one store wavefront = one full line
            st_rlx(hp + (size_t)t * HIDN + b * 16 + tid, h);
        }
        // no trailing barrier: hs4/gsum reuse is fenced by the two barriers
        // inside the next iteration
    }
}

// ---------------- feats = [h_f ; h_b] @ h2t_w^T + h2t_b ---------------------
__global__ void feats_kernel(const float* __restrict__ h2t_w,
                             const float* __restrict__ h2t_b) {
    int t = blockIdx.x;
    int tid = threadIdx.x;
    int w = tid >> 5, lane = tid & 31;
    const float* hf = g_h[0] + (size_t)t * HIDN;
    const float* hb = g_h[1] + (size_t)t * HIDN;
    const float* wr = h2t_w + w * (2 * HIDN);
    float acc = 0.0f;
    #pragma unroll
    for (int it = 0; it < 16; it++) {
        int k = lane + it * 32;
        acc += wr[k] * hf[k];
        acc += wr[512 + k] * hb[k];
    }
    #pragma unroll
    for (int o = 16; o > 0; o >>= 1) acc += __shfl_down_sync(0xffffffffu, acc, o);
    if (lane == 0) g_feats[t * 16 + w] = acc + h2t_b[w];
}

// ---------------- Viterbi + backtrack ---------------------------------------
__global__ void viterbi_kernel(const float* __restrict__ trans,
                               float* __restrict__ out, int out_size) {
    __shared__ unsigned char bp[SEQ][NTAG];   // 45 KB
    __shared__ float fbuf[32 * 16];           // 2 KB chunk of feats
    __shared__ float fvv[NTAG];
    int tid = threadIdx.x;
    int w = tid >> 5, lane = tid & 31;

    float trow[NTAG];
    float fv = NEGV;
    if (w == 0) {
        #pragma unroll
        for (int jj = 0; jj < NTAG; jj++)
            trow[jj] = (lane < NTAG) ? trans[lane * NTAG + jj] : NEGV;
        if (lane == STARTT) fv = 0.0f;
    }

    for (int c = 0; c < SEQ / 32; c++) {
        ((float4*)fbuf)[tid] = ((const float4*)(g_feats + c * 32 * 16))[tid];
        __syncthreads();
        if (w == 0) {
            #pragma unroll 4
            for (int tt = 0; tt < 32; tt++) {
                int t = c * 32 + tt;
                float featv = (lane < NTAG) ? fbuf[tt * 16 + lane] : 0.0f;
                float best = -3.4e38f; int arg = 0;
                #pragma unroll
                for (int jj = 0; jj < NTAG; jj++) {
                    float vj = __shfl_sync(0xffffffffu, fv, jj) + trow[jj];
                    if (vj > best) { best = vj; arg = jj; }
                }
                fv = best + featv;
                if (lane < NTAG) bp[t][lane] = (unsigned char)arg;
            }
        }
        __syncthreads();
    }

    if (w == 0 && lane < NTAG) fvv[lane] = fv;
    __syncthreads();

    if (tid == 0) {
        float bestv = -3.4e38f; int bi = 0;
        #pragma unroll
        for (int i = 0; i < NTAG; i++) {
            float v = fvv[i] + trans[STOPT * NTAG + i];
            if (i == STARTT || i == STOPT) v = NEGV;
            if (v > bestv) { bestv = v; bi = i; }
        }
        if (out_size > 0) out[0] = bestv;
        int tag = bi;
        for (int t = SEQ - 1; t >= 0; t--) {
            if (1 + t < out_size) out[1 + t] = (float)tag;
            tag = bp[t][tag];
        }
    }
}

// ---------------- launch --------------------------------------------------
extern "C" void kernel_launch(void* const* d_in, const int* in_sizes, int n_in,
                              void* d_out, int out_size) {
    const int*   sentence = (const int*)d_in[0];
    const int*   chars    = (const int*)d_in[1];
    const float* word_emb = (const float*)d_in[4];
    const float* char_emb = (const float*)d_in[5];
    const float* conv_w   = (const float*)d_in[6];
    const float* conv_b   = (const float*)d_in[7];
    const float* Wih_f    = (const float*)d_in[8];
    const float* Whh_f    = (const float*)d_in[9];
    const float* bih_f    = (const float*)d_in[10];
    const float* bhh_f    = (const float*)d_in[11];
    const float* Wih_b    = (const float*)d_in[12];
    const float* Whh_b    = (const float*)d_in[13];
    const float* bih_b    = (const float*)d_in[14];
    const float* bhh_b    = (const float*)d_in[15];
    const float* h2t_w    = (const float*)d_in[16];
    const float* h2t_b    = (const float*)d_in[17];
    const float* trans    = (const float*)d_in[18];
    float* out = (float*)d_out;

    embed_kernel<<<SEQ, 128>>>(sentence, chars, word_emb, char_emb, conv_w, conv_b);
    padw_kernel<<<(NGATE * EMBS + 255) / 256, 256>>>(Wih_f, Wih_b);
    dim3 gg(NGATE / 128, SEQ / 128, 2);
    gemm_kernel<<<gg, 256>>>(bih_f, bhh_f, bih_b, bhh_b);
    // poison AFTER the gemm (R14 win): sentinel lines stay L2-resident
    poison_kernel<<<4096, 256>>>();
    lstm_kernel<<<64, 512>>>(Whh_f, Whh_b);
    feats_kernel<<<SEQ, 352>>>(h2t_w, h2t_b);
    viterbi_kernel<<<1, 128>>>(trans, out, out_size);
}

// round 16
// speedup vs baseline: 1.1959x; 1.1959x over previous
#include <cuda_runtime.h>
#include <math.h>

#define SEQ   4096
#define LW    24
#define EMBD  300
#define CHOUT 25
#define CHE   25
#define HIDN  512
#define INPD  325      // EMB + CH_OUT
#define EMBS  336      // padded K (21 * 16) for vectorized GEMM
#define NTAG  11
#define STARTT 9
#define STOPT  10
#define NEGV  -10000.0f
#define NGATE 2048     // 4*HIDN
#define SENT  0x7FC00ABCu   // NaN payload sentinel: h in (-1,1) can never be NaN

typedef unsigned long long u64;

// ---------------- static device scratch (no allocs allowed) ----------------
__device__ float g_emb[SEQ * EMBS];             // 5.5 MB  [t][k], cols >=325 zero
__device__ float g_W[2][NGATE * EMBS];          // 5.5 MB  padded Wih
__device__ float g_G[2][SEQ * NGATE];           // 64 MB   Wih@x + bih + bhh
__device__ float g_h[2][SEQ * HIDN];            // 16 MB   hidden states (L2-resident)
__device__ float g_feats[SEQ * 16];             // padded [t][tag]

// ---------------- helpers ----------------
__device__ __forceinline__ float4 ld_rlx4(const float4* p) {
    float4 v;
    asm volatile("ld.relaxed.gpu.global.v4.f32 {%0,%1,%2,%3}, [%4];"
                 : "=f"(v.x), "=f"(v.y), "=f"(v.z), "=f"(v.w) : "l"(p));
    return v;
}
__device__ __forceinline__ void st_rlx(float* p, float v) {
    asm volatile("st.relaxed.gpu.global.f32 [%0], %1;" :: "l"(p), "f"(v));
}
__device__ __forceinline__ u64 fma2(u64 a, u64 b, u64 c) {
    u64 d;
    asm("fma.rn.f32x2 %0, %1, %2, %3;" : "=l"(d) : "l"(a), "l"(b), "l"(c));
    return d;
}
__device__ __forceinline__ u64 add2(u64 a, u64 b) {
    u64 d;
    asm("add.rn.f32x2 %0, %1, %2;" : "=l"(d) : "l"(a), "l"(b));
    return d;
}
__device__ __forceinline__ void upk2(u64 v, float& lo, float& hi) {
    asm("mov.b64 {%0,%1}, %2;" : "=f"(lo), "=f"(hi) : "l"(v));
}
__device__ __forceinline__ u64 pk2(float lo, float hi) {
    u64 d;
    asm("mov.b64 %0, {%1,%2};" : "=l"(d) : "f"(lo), "f"(hi));
    return d;
}
__device__ __forceinline__ float sigf(float x) {
    return __fdividef(1.0f, 1.0f + __expf(-x));
}
__device__ __forceinline__ float tanh_fast(float x) {
    return __fdividef(2.0f, 1.0f + __expf(-2.0f * x)) - 1.0f;
}

// ---------------- poison hidden-state buffer (data-as-flag protocol) --------
// Launched AFTER the GEMM (R14 win): the 16MB sentinel image must be the
// freshest data in L2 when the LSTM's polls start. If poison runs before the
// GEMM, the 64MB G write stream evicts it and every step's fastest consumers
// take a 577-cyc DRAM fetch before the producer's store lands.
__global__ void poison_kernel() {
    int i = blockIdx.x * blockDim.x + threadIdx.x;   // 1M float4 = 16 MB
    float s = __uint_as_float(SENT);
    ((float4*)&g_h[0][0])[i] = make_float4(s, s, s, s);
}

// ---------------- pad Wih into g_W (zero-filled K padding) ------------------
__global__ void padw_kernel(const float* __restrict__ Wf,
                            const float* __restrict__ Wb) {
    int i = blockIdx.x * blockDim.x + threadIdx.x;
    if (i >= NGATE * EMBS) return;
    int r = i / EMBS, k = i - r * EMBS;
    g_W[0][i] = (k < INPD) ? Wf[r * INPD + k] : 0.0f;
    g_W[1][i] = (k < INPD) ? Wb[r * INPD + k] : 0.0f;
}

// ---------------- char CNN + word-embedding gather --------------------------
__global__ void embed_kernel(const int* __restrict__ sentence,
                             const int* __restrict__ chars,
                             const float* __restrict__ word_emb,
                             const float* __restrict__ char_emb,
                             const float* __restrict__ conv_w,
                             const float* __restrict__ conv_b) {
    int s = blockIdx.x;
    int tid = threadIdx.x;
    __shared__ float ce[LW][CHE];
    __shared__ float co[CHOUT][26];
    __shared__ int   cidx[LW];

    if (tid < LW) cidx[tid] = chars[s * LW + tid];
    __syncthreads();
    for (int idx = tid; idx < LW * CHE; idx += blockDim.x) {
        int r = idx / CHE, e = idx % CHE;
        ce[r][e] = char_emb[cidx[r] * CHE + e];
    }
    __syncthreads();
    for (int idx = tid; idx < CHOUT * 26; idx += blockDim.x) {
        int o = idx / 26, p = idx % 26;
        float sum = 0.0f;
        #pragma unroll
        for (int kh = 0; kh < 3; kh++) {
            int r = p - 2 + kh;
            if (r >= 0 && r < LW) {
                const float* w = conv_w + (o * 3 + kh) * CHE;
                float ss = 0.0f;
                #pragma unroll
                for (int e = 0; e < CHE; e++) ss += ce[r][e] * w[e];
                sum += ss;
            }
        }
        co[o][p] = sum;
    }
    __syncthreads();
    if (tid < CHOUT) {
        float m = -3.4e38f;
        #pragma unroll
        for (int p = 0; p < 26; p++) m = fmaxf(m, co[tid][p]);
        g_emb[s * EMBS + EMBD + tid] = m + conv_b[tid];
    }
    if (tid < EMBS - INPD) g_emb[s * EMBS + INPD + tid] = 0.0f;  // zero K pad
    int wi = sentence[s];
    const float4* src = (const float4*)(word_emb + (size_t)wi * EMBD);
    float4* dst = (float4*)(g_emb + (size_t)s * EMBS);
    for (int i = tid; i < EMBD / 4; i += blockDim.x) dst[i] = src[i];
}

// ---------------- G = emb @ Wih^T + (bih + bhh) -----------------------------
// 128x128 tile, 256 threads, 8x8 microtile, packed f32x2 FMAs. (226us, kept.)
__global__ __launch_bounds__(256) void gemm_kernel(
    const float* __restrict__ bihf, const float* __restrict__ bhhf,
    const float* __restrict__ bihb, const float* __restrict__ bhhb) {
    int dir = blockIdx.z;
    const float* Wp = g_W[dir];
    const float* bih = dir ? bihb : bihf;
    const float* bhh = dir ? bhhb : bhhf;
    int bm = blockIdx.y * 128;
    int bn = blockIdx.x * 128;
    int tid = threadIdx.x;
    int tx = tid & 15, ty = tid >> 4;
    int lrow = tid >> 1, lk = (tid & 1) * 8;

    __shared__ __align__(16) float As[16][132];
    __shared__ __align__(16) float Bs[16][132];

    float bsum[8];
    #pragma unroll
    for (int j = 0; j < 4; j++) {
        int n0 = bn + tx * 4 + j, n1 = bn + 64 + tx * 4 + j;
        bsum[j] = bih[n0] + bhh[n0];
        bsum[4 + j] = bih[n1] + bhh[n1];
    }

    u64 acc[8][4] = {};

    for (int k0 = 0; k0 < EMBS; k0 += 16) {
        const float* ap = g_emb + (size_t)(bm + lrow) * EMBS + k0 + lk;
        const float* bp = Wp + (size_t)(bn + lrow) * EMBS + k0 + lk;
        float4 a0 = *(const float4*)ap;
        float4 a1 = *(const float4*)(ap + 4);
        float4 b0 = *(const float4*)bp;
        float4 b1 = *(const float4*)(bp + 4);
        __syncthreads();
        As[lk + 0][lrow] = a0.x; As[lk + 1][lrow] = a0.y;
        As[lk + 2][lrow] = a0.z; As[lk + 3][lrow] = a0.w;
        As[lk + 4][lrow] = a1.x; As[lk + 5][lrow] = a1.y;
        As[lk + 6][lrow] = a1.z; As[lk + 7][lrow] = a1.w;
        Bs[lk + 0][lrow] = b0.x; Bs[lk + 1][lrow] = b0.y;
        Bs[lk + 2][lrow] = b0.z; Bs[lk + 3][lrow] = b0.w;
        Bs[lk + 4][lrow] = b1.x; Bs[lk + 5][lrow] = b1.y;
        Bs[lk + 6][lrow] = b1.z; Bs[lk + 7][lrow] = b1.w;
        __syncthreads();
        #pragma unroll
        for (int kk = 0; kk < 16; kk++) {
            float4 af0 = *(const float4*)&As[kk][ty * 4];
            float4 af1 = *(const float4*)&As[kk][64 + ty * 4];
            float4 bf0 = *(const float4*)&Bs[kk][tx * 4];
            float4 bf1 = *(const float4*)&Bs[kk][64 + tx * 4];
            u64 bb0 = pk2(bf0.x, bf0.y), bb1 = pk2(bf0.z, bf0.w);
            u64 bb2 = pk2(bf1.x, bf1.y), bb3 = pk2(bf1.z, bf1.w);
            float aarr[8] = {af0.x, af0.y, af0.z, af0.w,
                             af1.x, af1.y, af1.z, af1.w};
            #pragma unroll
            for (int i = 0; i < 8; i++) {
                u64 aa = pk2(aarr[i], aarr[i]);
                acc[i][0] = fma2(aa, bb0, acc[i][0]);
                acc[i][1] = fma2(aa, bb1, acc[i][1]);
                acc[i][2] = fma2(aa, bb2, acc[i][2]);
                acc[i][3] = fma2(aa, bb3, acc[i][3]);
            }
        }
    }

    float* Gp = g_G[dir];
    #pragma unroll
    for (int i = 0; i < 8; i++) {
        int t = bm + ((i < 4) ? (ty * 4 + i) : (64 + ty * 4 + (i - 4)));
        float o[8];
        upk2(acc[i][0], o[0], o[1]); upk2(acc[i][1], o[2], o[3]);
        upk2(acc[i][2], o[4], o[5]); upk2(acc[i][3], o[6], o[7]);
        float4 v0 = make_float4(o[0] + bsum[0], o[1] + bsum[1],
                                o[2] + bsum[2], o[3] + bsum[3]);
        float4 v1 = make_float4(o[4] + bsum[4], o[5] + bsum[5],
                                o[6] + bsum[6], o[7] + bsum[7]);
        *(float4*)(Gp + (size_t)t * NGATE + bn + tx * 4) = v0;
        *(float4*)(Gp + (size_t)t * NGATE + bn + 64 + tx * 4) = v1;
    }
}

// ---------------- persistent BiLSTM recurrence -------------------------------
// Byte-exact R14 LSTM (best measured: 5780us total): 128 blocks (64/dir),
// 256 threads. Streaming __ldcs G prefetch; whole-vec4 sentinel polling on
// warps 0-3; gsum SMEM reduce; tid<8 gates (ILP-overlapped MUFU chains);
// 8-lane coalesced 32B store.
__global__ __launch_bounds__(256, 1) void lstm_kernel(
    const float* __restrict__ Whhf, const float* __restrict__ Whhb) {
    int dir = blockIdx.x >> 6;
    int b = blockIdx.x & 63;
    int tid = threadIdx.x;
    int lr = tid >> 3;     // local gate row 0..31
    int cg = tid & 7;      // column group (64 cols each)
    int gate = lr >> 3, jj = lr & 7;
    int grow = gate * HIDN + b * 8 + jj;
    const float* Whh = dir ? Whhb : Whhf;

    // 64 weights per thread in registers for the whole sequence
    ulonglong2 wgt[16];
    {
        const ulonglong2* wsrc = (const ulonglong2*)(Whh + (size_t)grow * HIDN + cg * 64);
        #pragma unroll
        for (int q = 0; q < 16; q++) wgt[q] = wsrc[q];
    }

    __shared__ float4 hs4[8 * 17];   // swizzled h_prev
    __shared__ float  gsum[32];

    const float* Gp = g_G[dir];
    float* hp = g_h[dir];
    float cstate = 0.0f;
    float gn0 = 0.f, gn1 = 0.f, gn2 = 0.f, gn3 = 0.f;

    // prefetch G for step 0 (streaming loads: do not pollute L2)
    if (tid < 8) {
        int t0 = dir ? (SEQ - 1) : 0;
        const float* gr = Gp + (size_t)t0 * NGATE + b * 8 + tid;
        gn0 = __ldcs(gr);        gn1 = __ldcs(gr + 512);
        gn2 = __ldcs(gr + 1024); gn3 = __ldcs(gr + 1536);
    }

    for (int s = 0; s < SEQ; s++) {
        int t = dir ? (SEQ - 1 - s) : s;
        float gi = gn0, gf = gn1, gg = gn2, go = gn3;
        if (tid < 8 && s + 1 < SEQ) {
            int tn = dir ? (t - 1) : (t + 1);
            const float* gr = Gp + (size_t)tn * NGATE + b * 8 + tid;
            gn0 = __ldcs(gr);        gn1 = __ldcs(gr + 512);
            gn2 = __ldcs(gr + 1024); gn3 = __ldcs(gr + 1536);
        }

        if (s > 0) {
            int pt = dir ? (t + 1) : (t - 1);
            if (tid < 128) {
                const float4* src = (const float4*)(hp + (size_t)pt * HIDN) + tid;
                float4 v;
                do {
                    v = ld_rlx4(src);
                } while (__float_as_uint(v.x) == SENT || __float_as_uint(v.y) == SENT ||
                         __float_as_uint(v.z) == SENT || __float_as_uint(v.w) == SENT);
                hs4[(tid >> 4) * 17 + (tid & 15)] = v;
            }
        } else {
            if (tid < 136) hs4[tid] = make_float4(0.f, 0.f, 0.f, 0.f);
        }
        __syncthreads();

        // partial dot: 64 columns per thread via packed f32x2 FMAs
        const ulonglong2* hrow = (const ulonglong2*)(hs4 + cg * 17);
        u64 a0 = 0ULL, a1 = 0ULL, a2 = 0ULL, a3 = 0ULL;
        #pragma unroll
        for (int q = 0; q < 16; q += 2) {
            ulonglong2 h0 = hrow[q];
            ulonglong2 h1 = hrow[q + 1];
            a0 = fma2(wgt[q].x, h0.x, a0);
            a1 = fma2(wgt[q].y, h0.y, a1);
            a2 = fma2(wgt[q + 1].x, h1.x, a2);
            a3 = fma2(wgt[q + 1].y, h1.y, a3);
        }
        float lo, hi;
        upk2(add2(add2(a0, a1), add2(a2, a3)), lo, hi);
        float acc = lo + hi;
        acc += __shfl_xor_sync(0xffffffffu, acc, 4);
        acc += __shfl_xor_sync(0xffffffffu, acc, 2);
        acc += __shfl_xor_sync(0xffffffffu, acc, 1);
        if (cg == 0) gsum[lr] = acc;
        __syncthreads();

        // gates: single warp, lanes 0..7 (independent MUFU chains overlap)
        if (tid < 8) {
            float vi = sigf(gi + gsum[tid]);
            float vf = sigf(gf + gsum[8 + tid]);
            float vg = tanh_fast(gg + gsum[16 + tid]);
            float vo = sigf(go + gsum[24 + tid]);
            cstate = vf * cstate + vi * vg;
            float h = vo * tanh_fast(cstate);
            // 8 lanes, contiguous 32B: one coalesced store wavefront
            st_rlx(hp + (size_t)t * HIDN + b * 8 + tid, h);
        }
        // no trailing barrier: hs4/gsum reuse is fenced by the two barriers
        // inside the next iteration
    }
}

// ---------------- feats = [h_f ; h_b] @ h2t_w^T + h2t_b ---------------------
__global__ void feats_kernel(const float* __restrict__ h2t_w,
                             const float* __restrict__ h2t_b) {
    int t = blockIdx.x;
    int tid = threadIdx.x;
    int w = tid >> 5, lane = tid & 31;
    const float* hf = g_h[0] + (size_t)t * HIDN;
    const float* hb = g_h[1] + (size_t)t * HIDN;
    const float* wr = h2t_w + w * (2 * HIDN);
    float acc = 0.0f;
    #pragma unroll
    for (int it = 0; it < 16; it++) {
        int k = lane + it * 32;
        acc += wr[k] * hf[k];
        acc += wr[512 + k] * hb[k];
    }
    #pragma unroll
    for (int o = 16; o > 0; o >>= 1) acc += __shfl_down_sync(0xffffffffu, acc, o);
    if (lane == 0) g_feats[t * 16 + w] = acc + h2t_b[w];
}

// ---------------- Viterbi + backtrack ---------------------------------------
__global__ void viterbi_kernel(const float* __restrict__ trans,
                               float* __restrict__ out, int out_size) {
    __shared__ unsigned char bp[SEQ][NTAG];   // 45 KB
    __shared__ float fbuf[32 * 16];           // 2 KB chunk of feats
    __shared__ float fvv[NTAG];
    int tid = threadIdx.x;
    int w = tid >> 5, lane = tid & 31;

    float trow[NTAG];
    float fv = NEGV;
    if (w == 0) {
        #pragma unroll
        for (int jj = 0; jj < NTAG; jj++)
            trow[jj] = (lane < NTAG) ? trans[lane * NTAG + jj] : NEGV;
        if (lane == STARTT) fv = 0.0f;
    }

    for (int c = 0; c < SEQ / 32; c++) {
        ((float4*)fbuf)[tid] = ((const float4*)(g_feats + c * 32 * 16))[tid];
        __syncthreads();
        if (w == 0) {
            #pragma unroll 4
            for (int tt = 0; tt < 32; tt++) {
                int t = c * 32 + tt;
                float featv = (lane < NTAG) ? fbuf[tt * 16 + lane] : 0.0f;
                float best = -3.4e38f; int arg = 0;
                #pragma unroll
                for (int jj = 0; jj < NTAG; jj++) {
                    float vj = __shfl_sync(0xffffffffu, fv, jj) + trow[jj];
                    if (vj > best) { best = vj; arg = jj; }
                }
                fv = best + featv;
                if (lane < NTAG) bp[t][lane] = (unsigned char)arg;
            }
        }
        __syncthreads();
    }

    if (w == 0 && lane < NTAG) fvv[lane] = fv;
    __syncthreads();

    if (tid == 0) {
        float bestv = -3.4e38f; int bi = 0;
        #pragma unroll
        for (int i = 0; i < NTAG; i++) {
            float v = fvv[i] + trans[STOPT * NTAG + i];
            if (i == STARTT || i == STOPT) v = NEGV;
            if (v > bestv) { bestv = v; bi = i; }
        }
        if (out_size > 0) out[0] = bestv;
        int tag = bi;
        for (int t = SEQ - 1; t >= 0; t--) {
            if (1 + t < out_size) out[1 + t] = (float)tag;
            tag = bp[t][tag];
        }
    }
}

// ---------------- launch --------------------------------------------------
extern "C" void kernel_launch(void* const* d_in, const int* in_sizes, int n_in,
                              void* d_out, int out_size) {
    const int*   sentence = (const int*)d_in[0];
    const int*   chars    = (const int*)d_in[1];
    const float* word_emb = (const float*)d_in[4];
    const float* char_emb = (const float*)d_in[5];
    const float* conv_w   = (const float*)d_in[6];
    const float* conv_b   = (const float*)d_in[7];
    const float* Wih_f    = (const float*)d_in[8];
    const float* Whh_f    = (const float*)d_in[9];
    const float* bih_f    = (const float*)d_in[10];
    const float* bhh_f    = (const float*)d_in[11];
    const float* Wih_b    = (const float*)d_in[12];
    const float* Whh_b    = (const float*)d_in[13];
    const float* bih_b    = (const float*)d_in[14];
    const float* bhh_b    = (const float*)d_in[15];
    const float* h2t_w    = (const float*)d_in[16];
    const float* h2t_b    = (const float*)d_in[17];
    const float* trans    = (const float*)d_in[18];
    float* out = (float*)d_out;

    embed_kernel<<<SEQ, 128>>>(sentence, chars, word_emb, char_emb, conv_w, conv_b);
    padw_kernel<<<(NGATE * EMBS + 255) / 256, 256>>>(Wih_f, Wih_b);
    dim3 gg(NGATE / 128, SEQ / 128, 2);
    gemm_kernel<<<gg, 256>>>(bih_f, bhh_f, bih_b, bhh_b);
    // poison AFTER the gemm (R14 win): sentinel lines stay L2-resident
    poison_kernel<<<4096, 256>>>();
    lstm_kernel<<<128, 256>>>(Whh_f, Whh_b);
    feats_kernel<<<SEQ, 352>>>(h2t_w, h2t_b);
    viterbi_kernel<<<1, 128>>>(trans, out, out_size);
}